// round 6
// baseline (speedup 1.0000x reference)
#include <cuda_runtime.h>
#include <math.h>
#include <stdint.h>

#define B_  8
#define S_  1024
#define H_  512
#define NH_ 8
#define HD_ 64

// Scratch (device globals). Values stored already tf32-quantized.
__device__ float g_q[B_*NH_*S_*HD_];   // [B,NH,S,HD], pre-scaled by 1/8
__device__ float g_k[B_*NH_*S_*HD_];   // [B,NH,S,HD]
__device__ float g_v[B_*NH_*S_*HD_];   // [B,NH,S,HD] row-major

__device__ __forceinline__ float to_tf32(float x) {
    unsigned u;
    asm("cvt.rna.tf32.f32 %0, %1;" : "=r"(u) : "f"(x));
    return __uint_as_float(u);
}

__device__ __forceinline__ void mma8(float c[4], const float a[4], float b0, float b1) {
    asm volatile(
        "mma.sync.aligned.m16n8k8.row.col.f32.tf32.tf32.f32 "
        "{%0,%1,%2,%3}, {%4,%5,%6,%7}, {%8,%9}, {%0,%1,%2,%3};\n"
        : "+f"(c[0]), "+f"(c[1]), "+f"(c[2]), "+f"(c[3])
        : "r"(__float_as_uint(a[0])), "r"(__float_as_uint(a[1])),
          "r"(__float_as_uint(a[2])), "r"(__float_as_uint(a[3])),
          "r"(__float_as_uint(b0)), "r"(__float_as_uint(b1)));
}

// ---------------------------------------------------------------------------
// Projection: out[m,n] = sum_k X[m,k] * W[n,k] + bias[n]
// grid: (64, 8, 3)  block: 256 (8 warps, 4x2, 32x32 per warp)
// ---------------------------------------------------------------------------
__global__ __launch_bounds__(256) void proj_kernel(
    const float* __restrict__ X,
    const float* __restrict__ Wq, const float* __restrict__ bq,
    const float* __restrict__ Wk, const float* __restrict__ bk,
    const float* __restrict__ Wv, const float* __restrict__ bv)
{
    __shared__ float Xs[128][36];
    __shared__ float Ws[64][36];

    const int zw = blockIdx.z;
    const float* W  = (zw == 0) ? Wq : (zw == 1) ? Wk : Wv;
    const float* bb = (zw == 0) ? bq : (zw == 1) ? bk : bv;
    float* dstbase  = (zw == 0) ? g_q : (zw == 1) ? g_k : g_v;
    const float osc = (zw == 0) ? 0.125f : 1.0f;

    const int m0 = blockIdx.x * 128;
    const int n0 = blockIdx.y * 64;
    const int tid  = threadIdx.x;
    const int lane = tid & 31;
    const int wid  = tid >> 5;
    const int wm = (wid & 3) * 32;
    const int wn = (wid >> 2) * 32;
    const int g = lane >> 2;
    const int t = lane & 3;

    float acc[2][4][4];
#pragma unroll
    for (int i = 0; i < 2; i++)
#pragma unroll
        for (int j = 0; j < 4; j++)
#pragma unroll
            for (int r = 0; r < 4; r++) acc[i][j][r] = 0.f;

    for (int kc = 0; kc < 512; kc += 32) {
#pragma unroll
        for (int p = 0; p < 4; p++) {
            int idx = tid + p * 256;
            int r = idx >> 3, c = (idx & 7) * 4;
            float4 v = *(const float4*)&X[(m0 + r) * 512 + kc + c];
            Xs[r][c + 0] = to_tf32(v.x); Xs[r][c + 1] = to_tf32(v.y);
            Xs[r][c + 2] = to_tf32(v.z); Xs[r][c + 3] = to_tf32(v.w);
        }
#pragma unroll
        for (int p = 0; p < 2; p++) {
            int idx = tid + p * 256;
            int r = idx >> 3, c = (idx & 7) * 4;
            float4 v = *(const float4*)&W[(n0 + r) * 512 + kc + c];
            Ws[r][c + 0] = to_tf32(v.x); Ws[r][c + 1] = to_tf32(v.y);
            Ws[r][c + 2] = to_tf32(v.z); Ws[r][c + 3] = to_tf32(v.w);
        }
        __syncthreads();

#pragma unroll
        for (int kk = 0; kk < 4; kk++) {
            float a[2][4];
#pragma unroll
            for (int i = 0; i < 2; i++) {
                int r = wm + i * 16 + g;
                a[i][0] = Xs[r    ][kk * 8 + t];
                a[i][1] = Xs[r + 8][kk * 8 + t];
                a[i][2] = Xs[r    ][kk * 8 + t + 4];
                a[i][3] = Xs[r + 8][kk * 8 + t + 4];
            }
#pragma unroll
            for (int j = 0; j < 4; j++) {
                int r = wn + j * 8 + g;
                float b0 = Ws[r][kk * 8 + t];
                float b1 = Ws[r][kk * 8 + t + 4];
#pragma unroll
                for (int i = 0; i < 2; i++) mma8(acc[i][j], a[i], b0, b1);
            }
        }
        __syncthreads();
    }

#pragma unroll
    for (int i = 0; i < 2; i++) {
#pragma unroll
        for (int j = 0; j < 4; j++) {
            int n = n0 + wn + j * 8 + t * 2;
            float b0 = bb[n], b1 = bb[n + 1];
            int h = n >> 6, d = n & 63;
#pragma unroll
            for (int rr = 0; rr < 2; rr++) {
                int m = m0 + wm + i * 16 + g + rr * 8;
                int bI = m >> 10, s = m & 1023;
                float2 v;
                v.x = to_tf32((acc[i][j][rr * 2 + 0] + b0) * osc);
                v.y = to_tf32((acc[i][j][rr * 2 + 1] + b1) * osc);
                *(float2*)&dstbase[(((bI * NH_ + h) * S_) + s) * HD_ + d] = v;
            }
        }
    }
}

// ---------------------------------------------------------------------------
// Flash attention, no-max-shift softmax (mathematically identical here).
// grid (16, NH, B) = 1024 CTAs, 128 threads = 4 warps (2 qg x 2 cg).
// Warp tile: 32 q-rows x 32 cols. k-block = 64.
// ---------------------------------------------------------------------------
#define KP_STRIDE  36    // float2 units
#define VS_STRIDE  138   // float units
#define PS_STRIDE  76    // float units
#define SM_KP_OFF  0
#define SM_VS_OFF  18432
#define SM_PS_OFF  (18432 + 17664)
#define SM_LQ_OFF  (18432 + 17664 + 19456)
#define ATTN_SMEM  (18432 + 17664 + 19456 + 512)

__global__ __launch_bounds__(128, 3) void attn_kernel(
    const float* __restrict__ rel,   // [B,NH,S,S]
    const float* __restrict__ mask,  // [B,1,1,S]
    float* __restrict__ out)         // [B,S,H]
{
    extern __shared__ char dsm[];
    float2* Kp  = (float2*)(dsm + SM_KP_OFF);
    float*  Vsf = (float*)(dsm + SM_VS_OFF);
    float*  Ps  = (float*)(dsm + SM_PS_OFF);
    float*  Lq  = (float*)(dsm + SM_LQ_OFF);

    const int b = blockIdx.z, h = blockIdx.y;
    const int q0 = blockIdx.x * 64;
    const int tid  = threadIdx.x;
    const int lane = tid & 31;
    const int wid  = tid >> 5;
    const int qg = wid >> 1;         // 0,1: q-group (32 rows each)
    const int cg = wid & 1;          // 0,1: column half
    const int g = lane >> 2;
    const int t = lane & 3;

    const int r0L = qg * 32 + g;     // warp-local base rows (mt0)
    const size_t bh = (size_t)(b * NH_ + h);

    // Q fragments resident: 2 m-tiles x 8 kk x 4 = 64 regs
    float qa[2][8][4];
    {
        const float* Qp = &g_q[(bh * S_ + q0 + qg * 32) * HD_];
#pragma unroll
        for (int mt = 0; mt < 2; mt++)
#pragma unroll
            for (int kk = 0; kk < 8; kk++) {
                int rr = mt * 16 + g;
                qa[mt][kk][0] = Qp[(rr    ) * 64 + kk * 8 + t];
                qa[mt][kk][1] = Qp[(rr + 8) * 64 + kk * 8 + t];
                qa[mt][kk][2] = Qp[(rr    ) * 64 + kk * 8 + t + 4];
                qa[mt][kk][3] = Qp[(rr + 8) * 64 + kk * 8 + t + 4];
            }
    }

    float o[2][4][4];
#pragma unroll
    for (int mt = 0; mt < 2; mt++)
#pragma unroll
        for (int nf = 0; nf < 4; nf++)
#pragma unroll
            for (int r = 0; r < 4; r++) o[mt][nf][r] = 0.f;

    float lacc[2][2] = {{0.f, 0.f}, {0.f, 0.f}};

    const float* Kg = &g_k[(bh * S_) * 64];
    const float* Vg = &g_v[(bh * S_) * 64];
    const float* mbase = mask + b * S_;
    // rel row pointers for the 4 rows this thread touches
    const float* rw[2][2];
#pragma unroll
    for (int mt = 0; mt < 2; mt++) {
        rw[mt][0] = rel + ((bh * S_) + q0 + qg * 32 + mt * 16 + g    ) * S_;
        rw[mt][1] = rel + ((bh * S_) + q0 + qg * 32 + mt * 16 + g + 8) * S_;
    }

    for (int kb = 0; kb < S_; kb += 64) {
        // ---- stage K [64 x 64] pair layout: slot(r, kk*4+j) = (K[r][kk*8+j], K[r][kk*8+j+4])
#pragma unroll
        for (int p = 0; p < 4; p++) {
            int idx = tid + p * 128;
            int r = idx >> 3, kk = idx & 7;
            const float* src = &Kg[(size_t)(kb + r) * 64 + kk * 8];
            float4 va = *(const float4*)src;
            float4 vb = *(const float4*)(src + 4);
            *(float4*)&Kp[r * KP_STRIDE + kk * 4]     = make_float4(va.x, vb.x, va.y, vb.y);
            *(float4*)&Kp[r * KP_STRIDE + kk * 4 + 2] = make_float4(va.z, vb.z, va.w, vb.w);
        }
        // ---- stage V [64 k x 64 d] row-pair layout:
        // Vsf[prow*138 + d*2 + sel] with prow=(k>>3)*4+(k&3), sel=(k&7)>>2
#pragma unroll
        for (int p = 0; p < 8; p++) {
            int idx = tid + p * 128;
            int r = idx & 63;
            int c4 = (idx >> 6) * 4;
            float4 v = *(const float4*)&Vg[(size_t)(kb + r) * 64 + c4];
            int prow = ((r >> 3) << 2) + (r & 3);
            int sel  = (r & 7) >> 2;
            float* dst = &Vsf[prow * VS_STRIDE + c4 * 2 + sel];
            dst[0] = v.x; dst[2] = v.y; dst[4] = v.z; dst[6] = v.w;
        }
        __syncthreads();

        // ---- S = Q K^T : warp computes rows [qg*32,+32) x cols [cg*32,+32)
        float s[2][4][4];
#pragma unroll
        for (int mt = 0; mt < 2; mt++)
#pragma unroll
            for (int nf = 0; nf < 4; nf++)
#pragma unroll
                for (int r = 0; r < 4; r++) s[mt][nf][r] = 0.f;
#pragma unroll
        for (int kk = 0; kk < 8; kk++) {
#pragma unroll
            for (int nf = 0; nf < 4; nf++) {
                float2 b2 = Kp[(cg * 32 + nf * 8 + g) * KP_STRIDE + kk * 4 + t];
                mma8(s[0][nf], qa[0][kk], b2.x, b2.y);
                mma8(s[1][nf], qa[1][kk], b2.x, b2.y);
            }
        }

        // ---- + rel + mask, exp (no shift), accumulate l, store P
#pragma unroll
        for (int mt = 0; mt < 2; mt++) {
#pragma unroll
            for (int nf = 0; nf < 4; nf++) {
                int colL = cg * 32 + nf * 8 + t * 2;
                int col  = kb + colL;
                float2 mk = *(const float2*)&mbase[col];
                float2 v0 = *(const float2*)&rw[mt][0][col];
                float2 v1 = *(const float2*)&rw[mt][1][col];
                float e00 = to_tf32(__expf(s[mt][nf][0] + v0.x + mk.x));
                float e01 = to_tf32(__expf(s[mt][nf][1] + v0.y + mk.y));
                float e10 = to_tf32(__expf(s[mt][nf][2] + v1.x + mk.x));
                float e11 = to_tf32(__expf(s[mt][nf][3] + v1.y + mk.y));
                lacc[mt][0] += e00 + e01;
                lacc[mt][1] += e10 + e11;
                int rowA = qg * 32 + mt * 16 + g;
                *(float2*)&Ps[(rowA    ) * PS_STRIDE + colL] = make_float2(e00, e01);
                *(float2*)&Ps[(rowA + 8) * PS_STRIDE + colL] = make_float2(e10, e11);
            }
        }
        __syncthreads();

        // ---- O += P V : warp rows [qg*32,+32) x d-cols [cg*32,+32)
#pragma unroll
        for (int kk = 0; kk < 8; kk++) {
            float a0[4], a1[4];
            a0[0] = Ps[(r0L     ) * PS_STRIDE + kk * 8 + t];
            a0[1] = Ps[(r0L +  8) * PS_STRIDE + kk * 8 + t];
            a0[2] = Ps[(r0L     ) * PS_STRIDE + kk * 8 + t + 4];
            a0[3] = Ps[(r0L +  8) * PS_STRIDE + kk * 8 + t + 4];
            a1[0] = Ps[(r0L + 16) * PS_STRIDE + kk * 8 + t];
            a1[1] = Ps[(r0L + 24) * PS_STRIDE + kk * 8 + t];
            a1[2] = Ps[(r0L + 16) * PS_STRIDE + kk * 8 + t + 4];
            a1[3] = Ps[(r0L + 24) * PS_STRIDE + kk * 8 + t + 4];
#pragma unroll
            for (int nf = 0; nf < 4; nf++) {
                int d = cg * 32 + nf * 8 + g;
                float2 vb = *(const float2*)&Vsf[(kk * 4 + t) * VS_STRIDE + d * 2];
                mma8(o[0][nf], a0, vb.x, vb.y);
                mma8(o[1][nf], a1, vb.x, vb.y);
            }
        }
        __syncthreads();
    }

    // ---- reduce l: quad sum, then combine cg halves via SMEM
#pragma unroll
    for (int mt = 0; mt < 2; mt++)
#pragma unroll
        for (int hh = 0; hh < 2; hh++) {
            float l = lacc[mt][hh];
            l += __shfl_xor_sync(0xffffffffu, l, 1);
            l += __shfl_xor_sync(0xffffffffu, l, 2);
            lacc[mt][hh] = l;
        }
    if (t == 0) {
#pragma unroll
        for (int mt = 0; mt < 2; mt++) {
            Lq[(qg * 32 + mt * 16 + g    ) * 2 + cg] = lacc[mt][0];
            Lq[(qg * 32 + mt * 16 + g + 8) * 2 + cg] = lacc[mt][1];
        }
    }
    __syncthreads();

    // ---- normalize + store
#pragma unroll
    for (int mt = 0; mt < 2; mt++) {
        int rA = qg * 32 + mt * 16 + g;
        float inv0 = 1.f / (Lq[rA * 2] + Lq[rA * 2 + 1]);
        float inv1 = 1.f / (Lq[(rA + 8) * 2] + Lq[(rA + 8) * 2 + 1]);
        float* op0 = out + ((size_t)(b * S_ + q0 + rA    )) * H_ + h * 64;
        float* op1 = out + ((size_t)(b * S_ + q0 + rA + 8)) * H_ + h * 64;
#pragma unroll
        for (int nf = 0; nf < 4; nf++) {
            int c = cg * 32 + nf * 8 + t * 2;
            *(float2*)&op0[c] = make_float2(o[mt][nf][0] * inv0, o[mt][nf][1] * inv0);
            *(float2*)&op1[c] = make_float2(o[mt][nf][2] * inv1, o[mt][nf][3] * inv1);
        }
    }
}

// ---------------------------------------------------------------------------
extern "C" void kernel_launch(void* const* d_in, const int* in_sizes, int n_in,
                              void* d_out, int out_size)
{
    const float* hidden = (const float*)d_in[0];
    const float* mask   = (const float*)d_in[1];
    const float* rel    = (const float*)d_in[2];
    const float* Wq     = (const float*)d_in[3];
    const float* bq     = (const float*)d_in[4];
    const float* Wk     = (const float*)d_in[5];
    const float* bk     = (const float*)d_in[6];
    const float* Wv     = (const float*)d_in[7];
    const float* bv     = (const float*)d_in[8];
    float* out = (float*)d_out;

    cudaFuncSetAttribute(attn_kernel, cudaFuncAttributeMaxDynamicSharedMemorySize,
                         ATTN_SMEM);

    dim3 pg(64, 8, 3);
    proj_kernel<<<pg, 256>>>(hidden, Wq, bq, Wk, bk, Wv, bv);

    dim3 ag(16, NH_, B_);
    attn_kernel<<<ag, 128, ATTN_SMEM>>>(rel, mask, out);
}

// round 8
// speedup vs baseline: 1.4167x; 1.4167x over previous
#include <cuda_runtime.h>
#include <math.h>
#include <stdint.h>

#define B_  8
#define S_  1024
#define H_  512
#define NH_ 8
#define HD_ 64

// Scratch (device globals). Values stored already tf32-quantized.
__device__ float g_q [B_*NH_*S_*HD_];   // [B,NH,S,HD], pre-scaled by 1/8
__device__ float g_k [B_*NH_*S_*HD_];   // [B,NH,S,HD]
__device__ float g_vt[B_*NH_*HD_*S_];   // [B,NH,HD,S] transposed V

__device__ __forceinline__ float to_tf32(float x) {
    unsigned u;
    asm("cvt.rna.tf32.f32 %0, %1;" : "=r"(u) : "f"(x));
    return __uint_as_float(u);
}

__device__ __forceinline__ void mma8(float c[4], const float a[4], float b0, float b1) {
    asm volatile(
        "mma.sync.aligned.m16n8k8.row.col.f32.tf32.tf32.f32 "
        "{%0,%1,%2,%3}, {%4,%5,%6,%7}, {%8,%9}, {%0,%1,%2,%3};\n"
        : "+f"(c[0]), "+f"(c[1]), "+f"(c[2]), "+f"(c[3])
        : "r"(__float_as_uint(a[0])), "r"(__float_as_uint(a[1])),
          "r"(__float_as_uint(a[2])), "r"(__float_as_uint(a[3])),
          "r"(__float_as_uint(b0)), "r"(__float_as_uint(b1)));
}

__device__ __forceinline__ uint32_t smem_u32(const void* p) {
    uint32_t a;
    asm("{ .reg .u64 t; cvta.to.shared.u64 t, %1; cvt.u32.u64 %0, t; }" : "=r"(a) : "l"(p));
    return a;
}
__device__ __forceinline__ void cp16(uint32_t smem, const float* g) {
    asm volatile("cp.async.cg.shared.global [%0], [%1], 16;" :: "r"(smem), "l"(g));
}

// ---------------------------------------------------------------------------
// Projection (round-1 version): out[m,n] = sum_k X[m,k]*W[n,k] + bias[n]
// grid (64, 8, 3), 256 threads.
// ---------------------------------------------------------------------------
__global__ __launch_bounds__(256) void proj_kernel(
    const float* __restrict__ X,
    const float* __restrict__ Wq, const float* __restrict__ bq,
    const float* __restrict__ Wk, const float* __restrict__ bk,
    const float* __restrict__ Wv, const float* __restrict__ bv)
{
    __shared__ float Xs[128][36];
    __shared__ float Ws[64][36];

    const int zw = blockIdx.z;
    const float* W  = (zw == 0) ? Wq : (zw == 1) ? Wk : Wv;
    const float* bb = (zw == 0) ? bq : (zw == 1) ? bk : bv;

    const int m0 = blockIdx.x * 128;
    const int n0 = blockIdx.y * 64;
    const int tid  = threadIdx.x;
    const int lane = tid & 31;
    const int wid  = tid >> 5;
    const int wm = (wid & 3) * 32;
    const int wn = (wid >> 2) * 32;
    const int g = lane >> 2;
    const int t = lane & 3;

    float acc[2][4][4];
#pragma unroll
    for (int i = 0; i < 2; i++)
#pragma unroll
        for (int j = 0; j < 4; j++)
#pragma unroll
            for (int r = 0; r < 4; r++) acc[i][j][r] = 0.f;

    for (int kc = 0; kc < 512; kc += 32) {
#pragma unroll
        for (int p = 0; p < 4; p++) {
            int idx = tid + p * 256;
            int r = idx >> 3, c = (idx & 7) * 4;
            float4 v = *(const float4*)&X[(m0 + r) * 512 + kc + c];
            Xs[r][c + 0] = to_tf32(v.x); Xs[r][c + 1] = to_tf32(v.y);
            Xs[r][c + 2] = to_tf32(v.z); Xs[r][c + 3] = to_tf32(v.w);
        }
#pragma unroll
        for (int p = 0; p < 2; p++) {
            int idx = tid + p * 256;
            int r = idx >> 3, c = (idx & 7) * 4;
            float4 v = *(const float4*)&W[(n0 + r) * 512 + kc + c];
            Ws[r][c + 0] = to_tf32(v.x); Ws[r][c + 1] = to_tf32(v.y);
            Ws[r][c + 2] = to_tf32(v.z); Ws[r][c + 3] = to_tf32(v.w);
        }
        __syncthreads();

#pragma unroll
        for (int kk = 0; kk < 4; kk++) {
            float a[2][4];
#pragma unroll
            for (int i = 0; i < 2; i++) {
                int r = wm + i * 16 + g;
                a[i][0] = Xs[r    ][kk * 8 + t];
                a[i][1] = Xs[r + 8][kk * 8 + t];
                a[i][2] = Xs[r    ][kk * 8 + t + 4];
                a[i][3] = Xs[r + 8][kk * 8 + t + 4];
            }
#pragma unroll
            for (int j = 0; j < 4; j++) {
                int r = wn + j * 8 + g;
                float b0 = Ws[r][kk * 8 + t];
                float b1 = Ws[r][kk * 8 + t + 4];
#pragma unroll
                for (int i = 0; i < 2; i++) mma8(acc[i][j], a[i], b0, b1);
            }
        }
        __syncthreads();
    }

#pragma unroll
    for (int i = 0; i < 2; i++) {
#pragma unroll
        for (int j = 0; j < 4; j++) {
            int n = n0 + wn + j * 8 + t * 2;
            float b0 = bb[n], b1 = bb[n + 1];
            int h = n >> 6, d = n & 63;
#pragma unroll
            for (int rr = 0; rr < 2; rr++) {
                int m = m0 + wm + i * 16 + g + rr * 8;
                int bI = m >> 10, s = m & 1023;
                float v0 = acc[i][j][rr * 2 + 0] + b0;
                float v1 = acc[i][j][rr * 2 + 1] + b1;
                if (zw == 0) {
                    float* dst = &g_q[(((bI * NH_ + h) * S_) + s) * HD_ + d];
                    dst[0] = to_tf32(v0 * 0.125f);
                    dst[1] = to_tf32(v1 * 0.125f);
                } else if (zw == 1) {
                    float* dst = &g_k[(((bI * NH_ + h) * S_) + s) * HD_ + d];
                    dst[0] = to_tf32(v0);
                    dst[1] = to_tf32(v1);
                } else {
                    g_vt[(((bI * NH_ + h) * HD_) + d    ) * S_ + s] = to_tf32(v0);
                    g_vt[(((bI * NH_ + h) * HD_) + d + 1) * S_ + s] = to_tf32(v1);
                }
            }
        }
    }
}

// ---------------------------------------------------------------------------
// Flash attention, no-max-shift softmax, cp.async double-buffered K/V,
// shuffle-based P fragment conversion (P never in SMEM).
// grid (8, NH, B), 256 threads = 8 warps x 16 q-rows, k-block 32.
// ---------------------------------------------------------------------------
__global__ __launch_bounds__(256, 2) void attn_kernel(
    const float* __restrict__ rel,   // [B,NH,S,S]
    const float* __restrict__ mask,  // [B,1,1,S]
    float* __restrict__ out)         // [B,S,H]
{
    __shared__ float Ksm[2][32][68];  // K block: [s_k][d], padded
    __shared__ float Vsm[2][64][36];  // Vt block: [d][s_k], padded

    const int b = blockIdx.z, h = blockIdx.y;
    const int q0 = blockIdx.x * 128;
    const int tid  = threadIdx.x;
    const int lane = tid & 31;
    const int wid  = tid >> 5;
    const int wq = wid * 16;
    const int g = lane >> 2;
    const int t = lane & 3;
    const size_t bh = (size_t)(b * NH_ + h);

    const float* Kg = &g_k[(bh * S_) * 64];
    const float* Vg = &g_vt[(bh * 64) * (size_t)S_];
    const float* mbase = mask + b * S_;
    const float* relrow0 = rel + (bh * S_ + q0 + wq + g    ) * S_;
    const float* relrow1 = rel + (bh * S_ + q0 + wq + g + 8) * S_;

    // cp.async staging assignments (2 x 16B chunks per thread per tile)
    // K: chunk c: row = c>>4, col16 = c&15
    const int kc0 = tid, kc1 = tid + 256;
    const uint32_t ks_base = smem_u32(&Ksm[0][0][0]);
    const uint32_t vs_base = smem_u32(&Vsm[0][0][0]);

    // Q fragments resident in registers
    float qa[8][4];
    {
        const float* Qp = &g_q[(bh * S_ + q0 + wq) * HD_];
#pragma unroll
        for (int kk = 0; kk < 8; kk++) {
            qa[kk][0] = Qp[(g    ) * 64 + kk * 8 + t];
            qa[kk][1] = Qp[(g + 8) * 64 + kk * 8 + t];
            qa[kk][2] = Qp[(g    ) * 64 + kk * 8 + t + 4];
            qa[kk][3] = Qp[(g + 8) * 64 + kk * 8 + t + 4];
        }
    }

    float o[8][4];
#pragma unroll
    for (int i = 0; i < 8; i++)
#pragma unroll
        for (int r = 0; r < 4; r++) o[i][r] = 0.f;

    float l0 = 0.f, l1 = 0.f;

    // ---- stage tile helper (inline) ----
#define STAGE_TILE(ITER, BUF) do {                                            \
        int _kb = (ITER) * 32;                                                \
        { int r = kc0 >> 4, c16 = kc0 & 15;                                   \
          cp16(ks_base + (BUF) * 8704u + r * 272u + c16 * 16u,                \
               &Kg[(size_t)(_kb + r) * 64 + c16 * 4]); }                      \
        { int r = kc1 >> 4, c16 = kc1 & 15;                                   \
          cp16(ks_base + (BUF) * 8704u + r * 272u + c16 * 16u,                \
               &Kg[(size_t)(_kb + r) * 64 + c16 * 4]); }                      \
        { int r = kc0 >> 3, c16 = kc0 & 7;                                    \
          cp16(vs_base + (BUF) * 9216u + r * 144u + c16 * 16u,                \
               &Vg[(size_t)r * S_ + _kb + c16 * 4]); }                        \
        { int r = kc1 >> 3, c16 = kc1 & 7;                                    \
          cp16(vs_base + (BUF) * 9216u + r * 144u + c16 * 16u,                \
               &Vg[(size_t)r * S_ + _kb + c16 * 4]); }                        \
    } while (0)

    STAGE_TILE(0, 0);
    asm volatile("cp.async.commit_group;");

    const int srcA = (g << 2) + (t >> 1);
    const int srcB = srcA + 2;
    const bool podd = (t & 1);

    for (int it = 0; it < 32; it++) {
        const int buf = it & 1;
        const int kb = it * 32;

        if (it + 1 < 32) {
            STAGE_TILE(it + 1, buf ^ 1);
            asm volatile("cp.async.commit_group;");
            asm volatile("cp.async.wait_group 1;");
        } else {
            asm volatile("cp.async.wait_group 0;");
        }
        __syncthreads();

        // rel/mask prefetch (overlaps QK MMAs below)
        float2 rv0[4], rv1[4], mk[4];
#pragma unroll
        for (int nf = 0; nf < 4; nf++) {
            int col = kb + nf * 8 + t * 2;
            mk[nf]  = *(const float2*)&mbase[col];
            rv0[nf] = *(const float2*)&relrow0[col];
            rv1[nf] = *(const float2*)&relrow1[col];
        }

        // ---- S = Q K^T (16 x 32)
        float s[4][4];
#pragma unroll
        for (int nf = 0; nf < 4; nf++)
#pragma unroll
            for (int r = 0; r < 4; r++) s[nf][r] = 0.f;
#pragma unroll
        for (int kk = 0; kk < 8; kk++) {
#pragma unroll
            for (int nf = 0; nf < 4; nf++) {
                float b0 = Ksm[buf][nf * 8 + g][kk * 8 + t];
                float b1 = Ksm[buf][nf * 8 + g][kk * 8 + t + 4];
                mma8(s[nf], qa[kk], b0, b1);
            }
        }

        // ---- + rel + mask, exp (no shift), accumulate l, quantize
#pragma unroll
        for (int nf = 0; nf < 4; nf++) {
            float e00 = to_tf32(__expf(s[nf][0] + rv0[nf].x + mk[nf].x));
            float e01 = to_tf32(__expf(s[nf][1] + rv0[nf].y + mk[nf].y));
            float e10 = to_tf32(__expf(s[nf][2] + rv1[nf].x + mk[nf].x));
            float e11 = to_tf32(__expf(s[nf][3] + rv1[nf].y + mk[nf].y));
            l0 += e00 + e01;
            l1 += e10 + e11;
            s[nf][0] = e00; s[nf][1] = e01; s[nf][2] = e10; s[nf][3] = e11;
        }

        // ---- O += P V : P C-frag -> A-frag via shuffles, V from SMEM
#pragma unroll
        for (int nf = 0; nf < 4; nf++) {
            float x0 = __shfl_sync(0xffffffffu, s[nf][0], srcA);
            float x1 = __shfl_sync(0xffffffffu, s[nf][1], srcA);
            float y0 = __shfl_sync(0xffffffffu, s[nf][2], srcA);
            float y1 = __shfl_sync(0xffffffffu, s[nf][3], srcA);
            float z0 = __shfl_sync(0xffffffffu, s[nf][0], srcB);
            float z1 = __shfl_sync(0xffffffffu, s[nf][1], srcB);
            float w0 = __shfl_sync(0xffffffffu, s[nf][2], srcB);
            float w1 = __shfl_sync(0xffffffffu, s[nf][3], srcB);
            float a[4];
            a[0] = podd ? x1 : x0;   // (row g,   k t)
            a[1] = podd ? y1 : y0;   // (row g+8, k t)
            a[2] = podd ? z1 : z0;   // (row g,   k t+4)
            a[3] = podd ? w1 : w0;   // (row g+8, k t+4)
#pragma unroll
            for (int nd = 0; nd < 8; nd++) {
                float b0 = Vsm[buf][nd * 8 + g][nf * 8 + t];
                float b1 = Vsm[buf][nd * 8 + g][nf * 8 + t + 4];
                mma8(o[nd], a, b0, b1);
            }
        }
        __syncthreads();
    }

    // ---- l reduce over quad (col partials live across t)
    l0 += __shfl_xor_sync(0xffffffffu, l0, 1);
    l0 += __shfl_xor_sync(0xffffffffu, l0, 2);
    l1 += __shfl_xor_sync(0xffffffffu, l1, 1);
    l1 += __shfl_xor_sync(0xffffffffu, l1, 2);
    float inv0 = 1.f / l0, inv1 = 1.f / l1;

    int q = q0 + wq + g;
    float* ob0 = &out[((size_t)(b * S_ + q    )) * H_ + h * 64];
    float* ob1 = &out[((size_t)(b * S_ + q + 8)) * H_ + h * 64];
#pragma unroll
    for (int nd = 0; nd < 8; nd++) {
        int c = nd * 8 + t * 2;
        *(float2*)&ob0[c] = make_float2(o[nd][0] * inv0, o[nd][1] * inv0);
        *(float2*)&ob1[c] = make_float2(o[nd][2] * inv1, o[nd][3] * inv1);
    }
}

// ---------------------------------------------------------------------------
extern "C" void kernel_launch(void* const* d_in, const int* in_sizes, int n_in,
                              void* d_out, int out_size)
{
    const float* hidden = (const float*)d_in[0];
    const float* mask   = (const float*)d_in[1];
    const float* rel    = (const float*)d_in[2];
    const float* Wq     = (const float*)d_in[3];
    const float* bq     = (const float*)d_in[4];
    const float* Wk     = (const float*)d_in[5];
    const float* bk     = (const float*)d_in[6];
    const float* Wv     = (const float*)d_in[7];
    const float* bv     = (const float*)d_in[8];
    float* out = (float*)d_out;

    dim3 pg(64, 8, 3);
    proj_kernel<<<pg, 256>>>(hidden, Wq, bq, Wk, bk, Wv, bv);

    dim3 ag(8, NH_, B_);
    attn_kernel<<<ag, 256>>>(rel, mask, out);
}